// round 1
// baseline (speedup 1.0000x reference)
#include <cuda_runtime.h>
#include <cstdint>

#define CODE_DIM 64
#define IN_DIM   68
#define HID      128
#define DT_MAXF  0.125f
#define NSTEPS   8
#define THREADS  512
#define NWARPS   (THREADS/32)
#define PPW      4
#define PPB      (NWARPS*PPW)

// ---- shared memory layout (float offsets), all float4-aligned ----
#define SM_W1   0
#define SM_B1   (SM_W1 + IN_DIM*HID)          // 8704
#define SM_W2   (SM_B1 + HID)                 // 8832
#define SM_B2   (SM_W2 + HID*HID)             // 25216
#define SM_W3   (SM_B2 + HID)                 // 25344 (padded [128][4])
#define SM_B3   (SM_W3 + HID*4)               // 25856
#define SM_CODE (SM_B3 + 4)                   // 25860, layout [k][point-in-block]
#define SM_STG  (SM_CODE + CODE_DIM*PPB)      // per-warp [k][p] staging
#define SM_WX   (SM_STG + NWARPS*HID*4)       // per-warp xyzt [coord][p]
#define SM_TOTAL (SM_WX + NWARPS*16)          // 38404 floats = 153616 B

__device__ __forceinline__ float ftanh(float x){
    // tanh(x) = 1 - 2/(e^{2x}+1); exact at limits, abs err ~1e-6
    float e = __expf(2.0f * x);
    return 1.0f - __fdividef(2.0f, e + 1.0f);
}

__device__ __forceinline__ void fma16(float acc[4][4], float4 xk, float4 wv){
    float xp[4] = {xk.x, xk.y, xk.z, xk.w};
    float wc[4] = {wv.x, wv.y, wv.z, wv.w};
#pragma unroll
    for (int p = 0; p < 4; p++)
#pragma unroll
        for (int c = 0; c < 4; c++)
            acc[p][c] = fmaf(xp[p], wc[c], acc[p][c]);
}

// acc[p][c] += sum_k stg[k][p] * W2[k][i4+c]
__device__ __forceinline__ void gemm_h(const float* __restrict__ stg,
                                       const float* __restrict__ W2s,
                                       int i4, float acc[4][4]){
#pragma unroll 4
    for (int k = 0; k < HID; k++){
        float4 hb = *(const float4*)(stg + k*4);           // broadcast: 4 points at k
        float4 wv = *(const float4*)(W2s + k*HID + i4);    // per-lane W chunk
        fma16(acc, hb, wv);
    }
}

__device__ __forceinline__ void reduce12(float sv[12]){
#pragma unroll
    for (int o = 16; o > 0; o >>= 1){
#pragma unroll
        for (int q = 0; q < 12; q++)
            sv[q] += __shfl_xor_sync(0xffffffffu, sv[q], o);
    }
}

__device__ __forceinline__ void stage4(float* __restrict__ stg, int i4, const float h[4][4]){
    __syncwarp();   // previous readers of stg done
#pragma unroll
    for (int c = 0; c < 4; c++){
        float4 v = make_float4(h[0][c], h[1][c], h[2][c], h[3][c]);
        *(float4*)(stg + (i4 + c)*4) = v;
    }
    __syncwarp();   // writes visible before reads
}

__device__ __forceinline__ void mlp_fwd(const float* __restrict__ sm,
        float* __restrict__ stg, const float* __restrict__ wx,
        int i4, int cbase,
        float h1[4][4], float h2[4][4], float vout[12])
{
    const float* W1s = sm + SM_W1;
    const float* b1s = sm + SM_B1;
    const float* W2s = sm + SM_W2;
    const float* b2s = sm + SM_B2;
    const float* W3s = sm + SM_W3;
    const float* b3s = sm + SM_B3;
    const float* codes = sm + SM_CODE;

    float acc[4][4];
    {
        float4 bv = *(const float4*)(b1s + i4);
#pragma unroll
        for (int p = 0; p < 4; p++){ acc[p][0]=bv.x; acc[p][1]=bv.y; acc[p][2]=bv.z; acc[p][3]=bv.w; }
    }
#pragma unroll 4
    for (int k = 0; k < CODE_DIM; k++){
        float4 xk = *(const float4*)(codes + k*PPB + cbase);
        float4 wv = *(const float4*)(W1s + k*HID + i4);
        fma16(acc, xk, wv);
    }
#pragma unroll
    for (int kk = 0; kk < 4; kk++){
        float4 xk = *(const float4*)(wx + kk*4);
        float4 wv = *(const float4*)(W1s + (CODE_DIM+kk)*HID + i4);
        fma16(acc, xk, wv);
    }
#pragma unroll
    for (int p = 0; p < 4; p++)
#pragma unroll
        for (int c = 0; c < 4; c++) h1[p][c] = ftanh(acc[p][c]);

    stage4(stg, i4, h1);

    {
        float4 bv = *(const float4*)(b2s + i4);
#pragma unroll
        for (int p = 0; p < 4; p++){ acc[p][0]=bv.x; acc[p][1]=bv.y; acc[p][2]=bv.z; acc[p][3]=bv.w; }
    }
    gemm_h(stg, W2s, i4, acc);
#pragma unroll
    for (int p = 0; p < 4; p++)
#pragma unroll
        for (int c = 0; c < 4; c++) h2[p][c] = ftanh(acc[p][c]);

    float sv[12];
#pragma unroll
    for (int q = 0; q < 12; q++) sv[q] = 0.f;
#pragma unroll
    for (int c = 0; c < 4; c++){
        float4 w3 = *(const float4*)(W3s + (i4 + c)*4);
#pragma unroll
        for (int p = 0; p < 4; p++){
            sv[p*3+0] = fmaf(h2[p][c], w3.x, sv[p*3+0]);
            sv[p*3+1] = fmaf(h2[p][c], w3.y, sv[p*3+1]);
            sv[p*3+2] = fmaf(h2[p][c], w3.z, sv[p*3+2]);
        }
    }
    reduce12(sv);
#pragma unroll
    for (int p = 0; p < 4; p++)
#pragma unroll
        for (int o = 0; o < 3; o++) vout[p*3+o] = sv[p*3+o] + b3s[o];
}

// forward-mode tangent wrt xyz_j: jout[p*3+o] = d v_o / d x_j (no bias)
__device__ __forceinline__ void mlp_tan(const float* __restrict__ sm,
        float* __restrict__ stg, int i4, int j,
        const float h1[4][4], const float h2[4][4], float jout[12])
{
    const float* W1s = sm + SM_W1;
    const float* W2s = sm + SM_W2;
    const float* W3s = sm + SM_W3;

    float4 wr = *(const float4*)(W1s + (CODE_DIM + j)*HID + i4);
    float wc[4] = {wr.x, wr.y, wr.z, wr.w};
    float dh1[4][4];
#pragma unroll
    for (int p = 0; p < 4; p++)
#pragma unroll
        for (int c = 0; c < 4; c++){
            float t = h1[p][c] * wc[c];
            dh1[p][c] = fmaf(-h1[p][c], t, wc[c]);    // (1-h1^2)*w
        }
    stage4(stg, i4, dh1);

    float acc[4][4];
#pragma unroll
    for (int p = 0; p < 4; p++)
#pragma unroll
        for (int c = 0; c < 4; c++) acc[p][c] = 0.f;
    gemm_h(stg, W2s, i4, acc);

    float sv[12];
#pragma unroll
    for (int q = 0; q < 12; q++) sv[q] = 0.f;
#pragma unroll
    for (int c = 0; c < 4; c++){
        float4 w3 = *(const float4*)(W3s + (i4 + c)*4);
#pragma unroll
        for (int p = 0; p < 4; p++){
            float t = h2[p][c] * acc[p][c];
            float d = fmaf(-h2[p][c], t, acc[p][c]);  // (1-h2^2)*acc
            sv[p*3+0] = fmaf(d, w3.x, sv[p*3+0]);
            sv[p*3+1] = fmaf(d, w3.y, sv[p*3+1]);
            sv[p*3+2] = fmaf(d, w3.z, sv[p*3+2]);
        }
    }
    reduce12(sv);
#pragma unroll
    for (int q = 0; q < 12; q++) jout[q] = sv[q];
}

__global__ void __launch_bounds__(THREADS, 1)
velwarp_kernel(const float* __restrict__ code_g, const float* __restrict__ pos_g,
               const float* __restrict__ t1_g, const float* __restrict__ t2_g,
               const float* __restrict__ W1_g, const float* __restrict__ b1_g,
               const float* __restrict__ W2_g, const float* __restrict__ b2_g,
               const float* __restrict__ W3_g, const float* __restrict__ b3_g,
               float* __restrict__ out, int n)
{
    extern __shared__ float sm[];
    const int tid  = threadIdx.x;
    const int w    = tid >> 5;
    const int lane = tid & 31;
    const int i4   = lane * 4;
    const int pbase = blockIdx.x * PPB;

    float* stg = sm + SM_STG + w * (HID*4);
    float* wx  = sm + SM_WX  + w * 16;

    // ---- cooperative loads: weights, biases, code tile (transposed to [k][p]) ----
    for (int idx = tid; idx < IN_DIM*HID; idx += THREADS) sm[SM_W1 + idx] = W1_g[idx];
    for (int idx = tid; idx < HID*HID;   idx += THREADS) sm[SM_W2 + idx] = W2_g[idx];
    if (tid < HID){
        sm[SM_B1 + tid] = b1_g[tid];
        sm[SM_B2 + tid] = b2_g[tid];
        sm[SM_W3 + tid*4 + 0] = W3_g[tid*3 + 0];
        sm[SM_W3 + tid*4 + 1] = W3_g[tid*3 + 1];
        sm[SM_W3 + tid*4 + 2] = W3_g[tid*3 + 2];
        sm[SM_W3 + tid*4 + 3] = 0.f;
    }
    if (tid < 4) sm[SM_B3 + tid] = (tid < 3) ? b3_g[tid] : 0.f;
    for (int idx = tid; idx < CODE_DIM*PPB; idx += THREADS){
        int p = idx >> 6;          // point in block
        int k = idx & 63;          // code component
        int gp = pbase + p;
        sm[SM_CODE + k*PPB + p] = (gp < n) ? code_g[(size_t)gp*CODE_DIM + k] : 0.f;
    }
    __syncthreads();

    const bool owner = (lane < PPW);
    const int  myp   = pbase + w*PPW + lane;
    const bool valid = owner && (myp < n);

    float px=0.f, py=0.f, pz=0.f, tt=0.f, off=0.f;
    float D[9] = {1,0,0, 0,1,0, 0,0,1};
    if (valid){
        px  = pos_g[(size_t)myp*3 + 0];
        py  = pos_g[(size_t)myp*3 + 1];
        pz  = pos_g[(size_t)myp*3 + 2];
        tt  = t1_g[myp];
        off = tt - t2_g[myp];
    }

    float h1[4][4], h2[4][4], v[12], jt[12];
    float jac[9];

#pragma unroll 1
    for (int s = 0; s < NSTEPS; s++){
        __syncwarp();
        if (owner){
            wx[0*4 + lane] = px; wx[1*4 + lane] = py;
            wx[2*4 + lane] = pz; wx[3*4 + lane] = tt;
        }
        __syncwarp();
        mlp_fwd(sm, stg, wx, i4, w*PPW, h1, h2, v);      // v0 at (xyz, t)

        float dt = 0.f;
        __syncwarp();
        if (owner){
            dt = copysignf(fminf(fabsf(off), DT_MAXF), off);
            wx[0*4 + lane] = fmaf(-0.5f*dt, v[lane*3+0], px);
            wx[1*4 + lane] = fmaf(-0.5f*dt, v[lane*3+1], py);
            wx[2*4 + lane] = fmaf(-0.5f*dt, v[lane*3+2], pz);
            wx[3*4 + lane] = tt - 0.5f*dt;
        }
        __syncwarp();
        mlp_fwd(sm, stg, wx, i4, w*PPW, h1, h2, v);      // velocity at midpoint

#pragma unroll
        for (int j = 0; j < 3; j++){
            mlp_tan(sm, stg, i4, j, h1, h2, jt);
            if (owner){
                jac[j*3+0] = jt[lane*3+0];
                jac[j*3+1] = jt[lane*3+1];
                jac[j*3+2] = jt[lane*3+2];
            }
        }

        if (owner){
            // drot[o][c] = sum_i jac_v[o][i] * D[i][c],  jac_v[o][i] = jac[i*3+o]
            float dr[9];
#pragma unroll
            for (int o = 0; o < 3; o++)
#pragma unroll
                for (int c = 0; c < 3; c++)
                    dr[o*3+c] = jac[0+o]*D[0*3+c] + jac[3+o]*D[1*3+c] + jac[6+o]*D[2*3+c];
#pragma unroll
            for (int q = 0; q < 9; q++) D[q] = fmaf(-dt, dr[q], D[q]);
            px = fmaf(-dt, v[lane*3+0], px);
            py = fmaf(-dt, v[lane*3+1], py);
            pz = fmaf(-dt, v[lane*3+2], pz);
            tt  -= dt;
            off -= dt;
        }
    }

    if (valid){
        out[(size_t)myp*3 + 0] = px;
        out[(size_t)myp*3 + 1] = py;
        out[(size_t)myp*3 + 2] = pz;
        float* od = out + (size_t)n*3 + (size_t)myp*9;
#pragma unroll
        for (int q = 0; q < 9; q++) od[q] = D[q];
    }
}

extern "C" void kernel_launch(void* const* d_in, const int* in_sizes, int n_in,
                              void* d_out, int out_size)
{
    const float* code = (const float*)d_in[0];
    const float* pos  = (const float*)d_in[1];
    const float* t1   = (const float*)d_in[2];
    const float* t2   = (const float*)d_in[3];
    const float* W1   = (const float*)d_in[4];
    const float* b1   = (const float*)d_in[5];
    const float* W2   = (const float*)d_in[6];
    const float* b2   = (const float*)d_in[7];
    const float* W3   = (const float*)d_in[8];
    const float* b3   = (const float*)d_in[9];

    const int n = in_sizes[2];                  // t1 has N elements
    const int blocks = (n + PPB - 1) / PPB;
    const size_t smem_bytes = (size_t)SM_TOTAL * sizeof(float);

    cudaFuncSetAttribute(velwarp_kernel,
                         cudaFuncAttributeMaxDynamicSharedMemorySize,
                         (int)smem_bytes);

    velwarp_kernel<<<blocks, THREADS, smem_bytes>>>(
        code, pos, t1, t2, W1, b1, W2, b2, W3, b3, (float*)d_out, n);
}

// round 2
// speedup vs baseline: 1.2046x; 1.2046x over previous
#include <cuda_runtime.h>
#include <cstdint>

#define CODE_DIM 64
#define IN_DIM   68
#define HID      128
#define DT_MAXF  0.125f
#define NSTEPS   8
#define THREADS  256
#define NWARPS   (THREADS/32)
#define PPW      8                     // points per warp
#define PPB      (NWARPS*PPW)          // 64 points per block

typedef unsigned long long ull;

// ---- shared memory layout (float offsets), all 16B-aligned ----
#define SM_W1   0
#define SM_B1   (SM_W1 + IN_DIM*HID)          // 8704
#define SM_W2   (SM_B1 + HID)                 // 8832
#define SM_B2   (SM_W2 + HID*HID)             // 25216
#define SM_W3   (SM_B2 + HID)                 // 25344, padded [128][4]
#define SM_B3   (SM_W3 + HID*4)               // 25856
#define SM_CODE (SM_B3 + 4)                   // 25860, layout [k][point-in-block]
#define SM_STG  (SM_CODE + CODE_DIM*PPB)      // 29956, per-warp [k][8]
#define SM_WX   (SM_STG + NWARPS*HID*PPW)     // 38148, per-warp [4][8]
#define SM_TOTAL (SM_WX + NWARPS*4*PPW)       // 38404 floats = 153616 B

__device__ __forceinline__ float ftanh(float x){
    float e = __expf(2.0f * x);
    return 1.0f - __fdividef(2.0f, e + 1.0f);
}

__device__ __forceinline__ ull ffma2(ull a, ull b, ull c){
    ull d;
    asm("fma.rn.f32x2 %0, %1, %2, %3;" : "=l"(d) : "l"(a), "l"(b), "l"(c));
    return d;
}
__device__ __forceinline__ ull pack2(float lo, float hi){
    ull d; asm("mov.b64 %0, {%1, %2};" : "=l"(d) : "f"(lo), "f"(hi)); return d;
}
__device__ __forceinline__ void unpack2(ull v, float& lo, float& hi){
    asm("mov.b64 {%0, %1}, %2;" : "=f"(lo), "=f"(hi) : "l"(v));
}

// acc[pair][col] += x[pair-of-points] * w[col] for 8 points x 4 cols.
// xrow: 8 floats (same k, points 0..7) -> two ulonglong2 = 4 packed pairs (free).
// wrow: 4 floats (this lane's column slice) -> duplicated into pairs (4 ALU packs).
__device__ __forceinline__ void fma_step8(ull acc[4][4],
        const float* __restrict__ xrow, const float* __restrict__ wrow){
    ulonglong2 xa = *(const ulonglong2*)(xrow);
    ulonglong2 xb = *(const ulonglong2*)(xrow + 4);
    float4 wv = *(const float4*)(wrow);
    ull wd0 = pack2(wv.x, wv.x), wd1 = pack2(wv.y, wv.y);
    ull wd2 = pack2(wv.z, wv.z), wd3 = pack2(wv.w, wv.w);
    ull xp0 = xa.x, xp1 = xa.y, xp2 = xb.x, xp3 = xb.y;
    acc[0][0]=ffma2(xp0,wd0,acc[0][0]); acc[0][1]=ffma2(xp0,wd1,acc[0][1]);
    acc[0][2]=ffma2(xp0,wd2,acc[0][2]); acc[0][3]=ffma2(xp0,wd3,acc[0][3]);
    acc[1][0]=ffma2(xp1,wd0,acc[1][0]); acc[1][1]=ffma2(xp1,wd1,acc[1][1]);
    acc[1][2]=ffma2(xp1,wd2,acc[1][2]); acc[1][3]=ffma2(xp1,wd3,acc[1][3]);
    acc[2][0]=ffma2(xp2,wd0,acc[2][0]); acc[2][1]=ffma2(xp2,wd1,acc[2][1]);
    acc[2][2]=ffma2(xp2,wd2,acc[2][2]); acc[2][3]=ffma2(xp2,wd3,acc[2][3]);
    acc[3][0]=ffma2(xp3,wd0,acc[3][0]); acc[3][1]=ffma2(xp3,wd1,acc[3][1]);
    acc[3][2]=ffma2(xp3,wd2,acc[3][2]); acc[3][3]=ffma2(xp3,wd3,acc[3][3]);
}

__device__ __forceinline__ void gemm_h8(const float* __restrict__ stg,
        const float* __restrict__ W2s, int i4, ull acc[4][4]){
#pragma unroll 4
    for (int k = 0; k < HID; k++)
        fma_step8(acc, stg + k*PPW, W2s + k*HID + i4);
}

__device__ __forceinline__ void acc_init_bias(ull acc[4][4], const float* bs, int i4){
    float4 bv = *(const float4*)(bs + i4);
    ull b0 = pack2(bv.x,bv.x), b1 = pack2(bv.y,bv.y);
    ull b2 = pack2(bv.z,bv.z), b3 = pack2(bv.w,bv.w);
#pragma unroll
    for (int pp = 0; pp < 4; pp++){ acc[pp][0]=b0; acc[pp][1]=b1; acc[pp][2]=b2; acc[pp][3]=b3; }
}

__device__ __forceinline__ void acc_tanh(const ull acc[4][4], float h[8][4]){
#pragma unroll
    for (int pp = 0; pp < 4; pp++)
#pragma unroll
        for (int c = 0; c < 4; c++){
            float a, b; unpack2(acc[pp][c], a, b);
            h[2*pp  ][c] = ftanh(a);
            h[2*pp+1][c] = ftanh(b);
        }
}

__device__ __forceinline__ void stage8(float* __restrict__ stg, int i4, const float h[8][4]){
    __syncwarp();
#pragma unroll
    for (int c = 0; c < 4; c++){
        *(float4*)(stg + (i4+c)*PPW)     = make_float4(h[0][c],h[1][c],h[2][c],h[3][c]);
        *(float4*)(stg + (i4+c)*PPW + 4) = make_float4(h[4][c],h[5][c],h[6][c],h[7][c]);
    }
    __syncwarp();
}

__device__ __forceinline__ void reduce24(float sv[24]){
#pragma unroll
    for (int o = 16; o > 0; o >>= 1)
#pragma unroll
        for (int q = 0; q < 24; q++)
            sv[q] += __shfl_xor_sync(0xffffffffu, sv[q], o);
}

// predicated extraction: owner lane (lane<8) takes point p == lane
__device__ __forceinline__ void extract3(const float sv[24], int lane,
                                         float& x, float& y, float& z){
    x = 0.f; y = 0.f; z = 0.f;
#pragma unroll
    for (int p = 0; p < 8; p++){
        bool s = (lane == p);
        x = s ? sv[p*3+0] : x;
        y = s ? sv[p*3+1] : y;
        z = s ? sv[p*3+2] : z;
    }
}

// forward MLP for 8 points; returns h1,h2 and owner-extracted velocity (+bias)
__device__ __forceinline__ void mlp_fwd8(const float* __restrict__ sm,
        float* __restrict__ stg, const float* __restrict__ wx,
        int i4, int cbase, int lane,
        float h1[8][4], float h2[8][4],
        float b3x, float b3y, float b3z,
        float& vx, float& vy, float& vz)
{
    const float* W1s = sm + SM_W1;
    const float* W2s = sm + SM_W2;
    const float* W3s = sm + SM_W3;
    const float* codes = sm + SM_CODE;

    ull acc[4][4];
    acc_init_bias(acc, sm + SM_B1, i4);
#pragma unroll 4
    for (int k = 0; k < CODE_DIM; k++)
        fma_step8(acc, codes + k*PPB + cbase, W1s + k*HID + i4);
#pragma unroll
    for (int kk = 0; kk < 4; kk++)
        fma_step8(acc, wx + kk*PPW, W1s + (CODE_DIM+kk)*HID + i4);
    acc_tanh(acc, h1);

    stage8(stg, i4, h1);
    acc_init_bias(acc, sm + SM_B2, i4);
    gemm_h8(stg, W2s, i4, acc);
    acc_tanh(acc, h2);

    float sv[24];
#pragma unroll
    for (int q = 0; q < 24; q++) sv[q] = 0.f;
#pragma unroll
    for (int c = 0; c < 4; c++){
        float4 w3 = *(const float4*)(W3s + (i4+c)*4);
#pragma unroll
        for (int p = 0; p < 8; p++){
            sv[p*3+0] = fmaf(h1? h2[p][c] : 0.f, w3.x, sv[p*3+0]); // h2 always
            sv[p*3+1] = fmaf(h2[p][c], w3.y, sv[p*3+1]);
            sv[p*3+2] = fmaf(h2[p][c], w3.z, sv[p*3+2]);
        }
    }
    reduce24(sv);
    extract3(sv, lane, vx, vy, vz);
    vx += b3x; vy += b3y; vz += b3z;
}

// tangent wrt x_j; returns owner-extracted (dv0,dv1,dv2)/dx_j (no bias)
__device__ __forceinline__ void mlp_tan8(const float* __restrict__ sm,
        float* __restrict__ stg, int i4, int j, int lane,
        const float h1[8][4], const float h2[8][4],
        float& jx, float& jy, float& jz)
{
    const float* W1s = sm + SM_W1;
    const float* W2s = sm + SM_W2;
    const float* W3s = sm + SM_W3;

    float4 wr = *(const float4*)(W1s + (CODE_DIM + j)*HID + i4);
    float wc[4] = {wr.x, wr.y, wr.z, wr.w};
    float dh1[8][4];
#pragma unroll
    for (int p = 0; p < 8; p++)
#pragma unroll
        for (int c = 0; c < 4; c++){
            float t = h1[p][c] * wc[c];
            dh1[p][c] = fmaf(-h1[p][c], t, wc[c]);       // (1-h1^2)*w
        }
    stage8(stg, i4, dh1);

    ull acc[4][4];
    ull z = pack2(0.f, 0.f);
#pragma unroll
    for (int pp = 0; pp < 4; pp++)
#pragma unroll
        for (int c = 0; c < 4; c++) acc[pp][c] = z;
    gemm_h8(stg, W2s, i4, acc);

    float sv[24];
#pragma unroll
    for (int q = 0; q < 24; q++) sv[q] = 0.f;
#pragma unroll
    for (int c = 0; c < 4; c++){
        float4 w3 = *(const float4*)(W3s + (i4+c)*4);
#pragma unroll
        for (int pp = 0; pp < 4; pp++){
            float a0, a1; unpack2(acc[pp][c], a0, a1);
            int p0 = 2*pp, p1 = 2*pp+1;
            float t0 = h2[p0][c] * a0;
            float d0 = fmaf(-h2[p0][c], t0, a0);         // (1-h2^2)*acc
            float t1 = h2[p1][c] * a1;
            float d1 = fmaf(-h2[p1][c], t1, a1);
            sv[p0*3+0] = fmaf(d0, w3.x, sv[p0*3+0]);
            sv[p0*3+1] = fmaf(d0, w3.y, sv[p0*3+1]);
            sv[p0*3+2] = fmaf(d0, w3.z, sv[p0*3+2]);
            sv[p1*3+0] = fmaf(d1, w3.x, sv[p1*3+0]);
            sv[p1*3+1] = fmaf(d1, w3.y, sv[p1*3+1]);
            sv[p1*3+2] = fmaf(d1, w3.z, sv[p1*3+2]);
        }
    }
    reduce24(sv);
    extract3(sv, lane, jx, jy, jz);
}

__global__ void __launch_bounds__(THREADS, 1)
velwarp_kernel(const float* __restrict__ code_g, const float* __restrict__ pos_g,
               const float* __restrict__ t1_g, const float* __restrict__ t2_g,
               const float* __restrict__ W1_g, const float* __restrict__ b1_g,
               const float* __restrict__ W2_g, const float* __restrict__ b2_g,
               const float* __restrict__ W3_g, const float* __restrict__ b3_g,
               float* __restrict__ out, int n)
{
    extern __shared__ float sm[];
    const int tid  = threadIdx.x;
    const int w    = tid >> 5;
    const int lane = tid & 31;
    const int i4   = lane * 4;
    const int pbase = blockIdx.x * PPB;

    float* stg = sm + SM_STG + w * (HID*PPW);
    float* wx  = sm + SM_WX  + w * (4*PPW);

    for (int idx = tid; idx < IN_DIM*HID; idx += THREADS) sm[SM_W1 + idx] = W1_g[idx];
    for (int idx = tid; idx < HID*HID;   idx += THREADS) sm[SM_W2 + idx] = W2_g[idx];
    if (tid < HID){
        sm[SM_B1 + tid] = b1_g[tid];
        sm[SM_B2 + tid] = b2_g[tid];
        sm[SM_W3 + tid*4 + 0] = W3_g[tid*3 + 0];
        sm[SM_W3 + tid*4 + 1] = W3_g[tid*3 + 1];
        sm[SM_W3 + tid*4 + 2] = W3_g[tid*3 + 2];
        sm[SM_W3 + tid*4 + 3] = 0.f;
    }
    if (tid < 4) sm[SM_B3 + tid] = (tid < 3) ? b3_g[tid] : 0.f;
    for (int idx = tid; idx < CODE_DIM*PPB; idx += THREADS){
        int p = idx >> 6;
        int k = idx & 63;
        int gp = pbase + p;
        sm[SM_CODE + k*PPB + p] = (gp < n) ? code_g[(size_t)gp*CODE_DIM + k] : 0.f;
    }
    __syncthreads();

    const float b3x = sm[SM_B3 + 0], b3y = sm[SM_B3 + 1], b3z = sm[SM_B3 + 2];

    const bool owner = (lane < PPW);
    const int  myp   = pbase + w*PPW + lane;
    const bool valid = owner && (myp < n);

    float px=0.f, py=0.f, pz=0.f, tt=0.f, off=0.f;
    float D[9] = {1,0,0, 0,1,0, 0,0,1};
    if (valid){
        px  = pos_g[(size_t)myp*3 + 0];
        py  = pos_g[(size_t)myp*3 + 1];
        pz  = pos_g[(size_t)myp*3 + 2];
        tt  = t1_g[myp];
        off = tt - t2_g[myp];
    }

    float h1[8][4], h2[8][4];
    float jac[9];

#pragma unroll 1
    for (int s = 0; s < NSTEPS; s++){
        __syncwarp();
        if (owner){
            wx[0*PPW + lane] = px; wx[1*PPW + lane] = py;
            wx[2*PPW + lane] = pz; wx[3*PPW + lane] = tt;
        }
        __syncwarp();
        float vx, vy, vz;
        mlp_fwd8(sm, stg, wx, i4, w*PPW, lane, h1, h2, b3x, b3y, b3z, vx, vy, vz);

        float dt = 0.f;
        __syncwarp();
        if (owner){
            dt = copysignf(fminf(fabsf(off), DT_MAXF), off);
            wx[0*PPW + lane] = fmaf(-0.5f*dt, vx, px);
            wx[1*PPW + lane] = fmaf(-0.5f*dt, vy, py);
            wx[2*PPW + lane] = fmaf(-0.5f*dt, vz, pz);
            wx[3*PPW + lane] = tt - 0.5f*dt;
        }
        __syncwarp();
        mlp_fwd8(sm, stg, wx, i4, w*PPW, lane, h1, h2, b3x, b3y, b3z, vx, vy, vz);

#pragma unroll
        for (int j = 0; j < 3; j++){
            float jx, jy, jz;
            mlp_tan8(sm, stg, i4, j, lane, h1, h2, jx, jy, jz);
            jac[j*3+0] = jx; jac[j*3+1] = jy; jac[j*3+2] = jz;
        }

        if (owner){
            // drot[o][c] = sum_i jac_v[o][i]*D[i][c],  jac[i*3+o] = jac_v[o][i]
            float dr[9];
#pragma unroll
            for (int o = 0; o < 3; o++)
#pragma unroll
                for (int c = 0; c < 3; c++)
                    dr[o*3+c] = jac[0+o]*D[0*3+c] + jac[3+o]*D[1*3+c] + jac[6+o]*D[2*3+c];
#pragma unroll
            for (int q = 0; q < 9; q++) D[q] = fmaf(-dt, dr[q], D[q]);
            px = fmaf(-dt, vx, px);
            py = fmaf(-dt, vy, py);
            pz = fmaf(-dt, vz, pz);
            tt  -= dt;
            off -= dt;
        }
    }

    if (valid){
        out[(size_t)myp*3 + 0] = px;
        out[(size_t)myp*3 + 1] = py;
        out[(size_t)myp*3 + 2] = pz;
        float* od = out + (size_t)n*3 + (size_t)myp*9;
#pragma unroll
        for (int q = 0; q < 9; q++) od[q] = D[q];
    }
}

extern "C" void kernel_launch(void* const* d_in, const int* in_sizes, int n_in,
                              void* d_out, int out_size)
{
    const float* code = (const float*)d_in[0];
    const float* pos  = (const float*)d_in[1];
    const float* t1   = (const float*)d_in[2];
    const float* t2   = (const float*)d_in[3];
    const float* W1   = (const float*)d_in[4];
    const float* b1   = (const float*)d_in[5];
    const float* W2   = (const float*)d_in[6];
    const float* b2   = (const float*)d_in[7];
    const float* W3   = (const float*)d_in[8];
    const float* b3   = (const float*)d_in[9];

    const int n = in_sizes[2];                  // t1 has N elements
    const int blocks = (n + PPB - 1) / PPB;
    const size_t smem_bytes = (size_t)SM_TOTAL * sizeof(float);

    cudaFuncSetAttribute(velwarp_kernel,
                         cudaFuncAttributeMaxDynamicSharedMemorySize,
                         (int)smem_bytes);

    velwarp_kernel<<<blocks, THREADS, smem_bytes>>>(
        code, pos, t1, t2, W1, b1, W2, b2, W3, b3, (float*)d_out, n);
}

// round 3
// speedup vs baseline: 1.9676x; 1.6334x over previous
#include <cuda_runtime.h>
#include <cstdint>

#define CODE_DIM 64
#define IN_DIM   68
#define HID      128
#define DT_MAXF  0.125f
#define NSTEPS   8
#define THREADS  256
#define NWARPS   (THREADS/32)
#define PPW      8
#define PPB      (NWARPS*PPW)          // 64 points per block
#define MAXN     (1<<18)

typedef unsigned long long ull;

// ---- scratch for bucketing (no allocs allowed) ----
__device__ int g_hist[16];
__device__ int g_cursor[16];
__device__ int g_perm[MAXN];

// ---- shared memory layout (float offsets), 16B-aligned ----
#define SM_W1   0
#define SM_B1   (SM_W1 + IN_DIM*HID)
#define SM_W2   (SM_B1 + HID)
#define SM_B2   (SM_W2 + HID*HID)
#define SM_W3   (SM_B2 + HID)                 // padded [128][4]
#define SM_B3   (SM_W3 + HID*4)
#define SM_CODE (SM_B3 + 4)                   // [k][point-in-block]
#define SM_STG  (SM_CODE + CODE_DIM*PPB)      // per-warp [k][8]
#define SM_WX   (SM_STG + NWARPS*HID*PPW)     // per-warp [4][8]
#define SM_TOTAL (SM_WX + NWARPS*4*PPW)       // 38404 floats = 153616 B

__device__ __forceinline__ float ftanh(float x){
    float e = __expf(2.0f * x);
    return 1.0f - __fdividef(2.0f, e + 1.0f);
}
__device__ __forceinline__ ull ffma2(ull a, ull b, ull c){
    ull d; asm("fma.rn.f32x2 %0, %1, %2, %3;" : "=l"(d) : "l"(a), "l"(b), "l"(c)); return d;
}
__device__ __forceinline__ ull pack2(float lo, float hi){
    ull d; asm("mov.b64 %0, {%1, %2};" : "=l"(d) : "f"(lo), "f"(hi)); return d;
}
__device__ __forceinline__ void unpack2(ull v, float& lo, float& hi){
    asm("mov.b64 {%0, %1}, %2;" : "=f"(lo), "=f"(hi) : "l"(v));
}

__device__ __forceinline__ void fma_step8(ull acc[4][4],
        const float* __restrict__ xrow, const float* __restrict__ wrow){
    ulonglong2 xa = *(const ulonglong2*)(xrow);
    ulonglong2 xb = *(const ulonglong2*)(xrow + 4);
    float4 wv = *(const float4*)(wrow);
    ull wd0 = pack2(wv.x, wv.x), wd1 = pack2(wv.y, wv.y);
    ull wd2 = pack2(wv.z, wv.z), wd3 = pack2(wv.w, wv.w);
    ull xp0 = xa.x, xp1 = xa.y, xp2 = xb.x, xp3 = xb.y;
    acc[0][0]=ffma2(xp0,wd0,acc[0][0]); acc[0][1]=ffma2(xp0,wd1,acc[0][1]);
    acc[0][2]=ffma2(xp0,wd2,acc[0][2]); acc[0][3]=ffma2(xp0,wd3,acc[0][3]);
    acc[1][0]=ffma2(xp1,wd0,acc[1][0]); acc[1][1]=ffma2(xp1,wd1,acc[1][1]);
    acc[1][2]=ffma2(xp1,wd2,acc[1][2]); acc[1][3]=ffma2(xp1,wd3,acc[1][3]);
    acc[2][0]=ffma2(xp2,wd0,acc[2][0]); acc[2][1]=ffma2(xp2,wd1,acc[2][1]);
    acc[2][2]=ffma2(xp2,wd2,acc[2][2]); acc[2][3]=ffma2(xp2,wd3,acc[2][3]);
    acc[3][0]=ffma2(xp3,wd0,acc[3][0]); acc[3][1]=ffma2(xp3,wd1,acc[3][1]);
    acc[3][2]=ffma2(xp3,wd2,acc[3][2]); acc[3][3]=ffma2(xp3,wd3,acc[3][3]);
}

__device__ __forceinline__ void gemm_h8(const float* __restrict__ stg,
        const float* __restrict__ W2s, int i4, ull acc[4][4]){
#pragma unroll 4
    for (int k = 0; k < HID; k++)
        fma_step8(acc, stg + k*PPW, W2s + k*HID + i4);
}

__device__ __forceinline__ void acc_init_bias(ull acc[4][4], const float* bs, int i4){
    float4 bv = *(const float4*)(bs + i4);
    ull b0 = pack2(bv.x,bv.x), b1 = pack2(bv.y,bv.y);
    ull b2 = pack2(bv.z,bv.z), b3 = pack2(bv.w,bv.w);
#pragma unroll
    for (int pp = 0; pp < 4; pp++){ acc[pp][0]=b0; acc[pp][1]=b1; acc[pp][2]=b2; acc[pp][3]=b3; }
}

__device__ __forceinline__ void acc_tanh(const ull acc[4][4], float h[8][4]){
#pragma unroll
    for (int pp = 0; pp < 4; pp++)
#pragma unroll
        for (int c = 0; c < 4; c++){
            float a, b; unpack2(acc[pp][c], a, b);
            h[2*pp  ][c] = ftanh(a);
            h[2*pp+1][c] = ftanh(b);
        }
}

__device__ __forceinline__ void stage8(float* __restrict__ stg, int i4, const float h[8][4]){
    __syncwarp();
#pragma unroll
    for (int c = 0; c < 4; c++){
        *(float4*)(stg + (i4+c)*PPW)     = make_float4(h[0][c],h[1][c],h[2][c],h[3][c]);
        *(float4*)(stg + (i4+c)*PPW + 4) = make_float4(h[4][c],h[5][c],h[6][c],h[7][c]);
    }
    __syncwarp();
}

__device__ __forceinline__ void reduce24(float sv[24]){
#pragma unroll
    for (int o = 16; o > 0; o >>= 1)
#pragma unroll
        for (int q = 0; q < 24; q++)
            sv[q] += __shfl_xor_sync(0xffffffffu, sv[q], o);
}

__device__ __forceinline__ void extract3(const float sv[24], int lane,
                                         float& x, float& y, float& z){
    x = 0.f; y = 0.f; z = 0.f;
#pragma unroll
    for (int p = 0; p < 8; p++){
        bool s = (lane == p);
        x = s ? sv[p*3+0] : x;
        y = s ? sv[p*3+1] : y;
        z = s ? sv[p*3+2] : z;
    }
}

__device__ __forceinline__ void mlp_fwd8(const float* __restrict__ sm,
        float* __restrict__ stg, const float* __restrict__ wx,
        int i4, int cbase, int lane,
        float h1[8][4], float h2[8][4],
        float b3x, float b3y, float b3z,
        float& vx, float& vy, float& vz)
{
    const float* W1s = sm + SM_W1;
    const float* W2s = sm + SM_W2;
    const float* W3s = sm + SM_W3;
    const float* codes = sm + SM_CODE;

    ull acc[4][4];
    acc_init_bias(acc, sm + SM_B1, i4);
#pragma unroll 4
    for (int k = 0; k < CODE_DIM; k++)
        fma_step8(acc, codes + k*PPB + cbase, W1s + k*HID + i4);
#pragma unroll
    for (int kk = 0; kk < 4; kk++)
        fma_step8(acc, wx + kk*PPW, W1s + (CODE_DIM+kk)*HID + i4);
    acc_tanh(acc, h1);

    stage8(stg, i4, h1);
    acc_init_bias(acc, sm + SM_B2, i4);
    gemm_h8(stg, W2s, i4, acc);
    acc_tanh(acc, h2);

    float sv[24];
#pragma unroll
    for (int q = 0; q < 24; q++) sv[q] = 0.f;
#pragma unroll
    for (int c = 0; c < 4; c++){
        float4 w3 = *(const float4*)(W3s + (i4+c)*4);
#pragma unroll
        for (int p = 0; p < 8; p++){
            sv[p*3+0] = fmaf(h2[p][c], w3.x, sv[p*3+0]);
            sv[p*3+1] = fmaf(h2[p][c], w3.y, sv[p*3+1]);
            sv[p*3+2] = fmaf(h2[p][c], w3.z, sv[p*3+2]);
        }
    }
    reduce24(sv);
    extract3(sv, lane, vx, vy, vz);
    vx += b3x; vy += b3y; vz += b3z;
}

__device__ __forceinline__ void mlp_tan8(const float* __restrict__ sm,
        float* __restrict__ stg, int i4, int j, int lane,
        const float h1[8][4], const float h2[8][4],
        float& jx, float& jy, float& jz)
{
    const float* W1s = sm + SM_W1;
    const float* W2s = sm + SM_W2;
    const float* W3s = sm + SM_W3;

    float4 wr = *(const float4*)(W1s + (CODE_DIM + j)*HID + i4);
    float wc[4] = {wr.x, wr.y, wr.z, wr.w};
    float dh1[8][4];
#pragma unroll
    for (int p = 0; p < 8; p++)
#pragma unroll
        for (int c = 0; c < 4; c++){
            float t = h1[p][c] * wc[c];
            dh1[p][c] = fmaf(-h1[p][c], t, wc[c]);
        }
    stage8(stg, i4, dh1);

    ull acc[4][4];
    ull z = pack2(0.f, 0.f);
#pragma unroll
    for (int pp = 0; pp < 4; pp++)
#pragma unroll
        for (int c = 0; c < 4; c++) acc[pp][c] = z;
    gemm_h8(stg, W2s, i4, acc);

    float sv[24];
#pragma unroll
    for (int q = 0; q < 24; q++) sv[q] = 0.f;
#pragma unroll
    for (int c = 0; c < 4; c++){
        float4 w3 = *(const float4*)(W3s + (i4+c)*4);
#pragma unroll
        for (int pp = 0; pp < 4; pp++){
            float a0, a1; unpack2(acc[pp][c], a0, a1);
            int p0 = 2*pp, p1 = 2*pp+1;
            float t0 = h2[p0][c] * a0;
            float d0 = fmaf(-h2[p0][c], t0, a0);
            float t1 = h2[p1][c] * a1;
            float d1 = fmaf(-h2[p1][c], t1, a1);
            sv[p0*3+0] = fmaf(d0, w3.x, sv[p0*3+0]);
            sv[p0*3+1] = fmaf(d0, w3.y, sv[p0*3+1]);
            sv[p0*3+2] = fmaf(d0, w3.z, sv[p0*3+2]);
            sv[p1*3+0] = fmaf(d1, w3.x, sv[p1*3+0]);
            sv[p1*3+1] = fmaf(d1, w3.y, sv[p1*3+1]);
            sv[p1*3+2] = fmaf(d1, w3.z, sv[p1*3+2]);
        }
    }
    reduce24(sv);
    extract3(sv, lane, jx, jy, jz);
}

// ---- bucketing pre-pass: counting sort of points by required step count ----
__device__ __forceinline__ int steps_needed(float off){
    float a = fabsf(off);
    int k = (int)ceilf(a * 8.0f);          // a*8 exact (pow2 scale)
    return k > NSTEPS ? NSTEPS : k;
}

__global__ void k_zero(){
    if (threadIdx.x < 16){ g_hist[threadIdx.x] = 0; g_cursor[threadIdx.x] = 0; }
}
__global__ void k_hist(const float* __restrict__ t1, const float* __restrict__ t2, int n){
    int i = blockIdx.x*blockDim.x + threadIdx.x;
    if (i < n) atomicAdd(&g_hist[steps_needed(t1[i]-t2[i])], 1);
}
__global__ void k_prefix(){
    if (threadIdx.x == 0){
        int s = 0;
#pragma unroll
        for (int b = 0; b <= NSTEPS; b++){ g_cursor[b] = s; s += g_hist[b]; }
    }
}
__global__ void k_scatter(const float* __restrict__ t1, const float* __restrict__ t2, int n){
    int i = blockIdx.x*blockDim.x + threadIdx.x;
    if (i < n){
        int k = steps_needed(t1[i]-t2[i]);
        int pos = atomicAdd(&g_cursor[k], 1);
        g_perm[pos] = i;
    }
}

__global__ void __launch_bounds__(THREADS, 1)
velwarp_kernel(const float* __restrict__ code_g, const float* __restrict__ pos_g,
               const float* __restrict__ t1_g, const float* __restrict__ t2_g,
               const float* __restrict__ W1_g, const float* __restrict__ b1_g,
               const float* __restrict__ W2_g, const float* __restrict__ b2_g,
               const float* __restrict__ W3_g, const float* __restrict__ b3_g,
               float* __restrict__ out, int n)
{
    extern __shared__ float sm[];
    const int tid  = threadIdx.x;
    const int w    = tid >> 5;
    const int lane = tid & 31;
    const int i4   = lane * 4;
    const int pbase = blockIdx.x * PPB;

    float* stg = sm + SM_STG + w * (HID*PPW);
    float* wx  = sm + SM_WX  + w * (4*PPW);

    for (int idx = tid; idx < IN_DIM*HID; idx += THREADS) sm[SM_W1 + idx] = W1_g[idx];
    for (int idx = tid; idx < HID*HID;   idx += THREADS) sm[SM_W2 + idx] = W2_g[idx];
    if (tid < HID){
        sm[SM_B1 + tid] = b1_g[tid];
        sm[SM_B2 + tid] = b2_g[tid];
        sm[SM_W3 + tid*4 + 0] = W3_g[tid*3 + 0];
        sm[SM_W3 + tid*4 + 1] = W3_g[tid*3 + 1];
        sm[SM_W3 + tid*4 + 2] = W3_g[tid*3 + 2];
        sm[SM_W3 + tid*4 + 3] = 0.f;
    }
    if (tid < 4) sm[SM_B3 + tid] = (tid < 3) ? b3_g[tid] : 0.f;
    for (int idx = tid; idx < CODE_DIM*PPB; idx += THREADS){
        int p = idx >> 6;
        int k = idx & 63;
        int slot = pbase + p;
        int gp = (slot < n) ? g_perm[slot] : -1;
        sm[SM_CODE + k*PPB + p] = (gp >= 0) ? code_g[(size_t)gp*CODE_DIM + k] : 0.f;
    }
    __syncthreads();

    const float b3x = sm[SM_B3 + 0], b3y = sm[SM_B3 + 1], b3z = sm[SM_B3 + 2];

    const bool owner = (lane < PPW);
    const int  slot  = pbase + w*PPW + lane;
    const int  myp   = (owner && slot < n) ? g_perm[slot] : -1;
    const bool valid = (myp >= 0);

    float px=0.f, py=0.f, pz=0.f, tt=0.f, off=0.f;
    float D[9] = {1,0,0, 0,1,0, 0,0,1};
    if (valid){
        px  = pos_g[(size_t)myp*3 + 0];
        py  = pos_g[(size_t)myp*3 + 1];
        pz  = pos_g[(size_t)myp*3 + 2];
        tt  = t1_g[myp];
        off = tt - t2_g[myp];
    }

    float h1[8][4], h2[8][4];
    float jac[9];

#pragma unroll 1
    for (int s = 0; s < NSTEPS; s++){
        // whole-warp early exit: all remaining steps are exact no-ops (dt==0)
        if (__ballot_sync(0xffffffffu, off != 0.0f) == 0u) break;

        __syncwarp();
        if (owner){
            wx[0*PPW + lane] = px; wx[1*PPW + lane] = py;
            wx[2*PPW + lane] = pz; wx[3*PPW + lane] = tt;
        }
        __syncwarp();
        float vx, vy, vz;
        mlp_fwd8(sm, stg, wx, i4, w*PPW, lane, h1, h2, b3x, b3y, b3z, vx, vy, vz);

        float dt = 0.f;
        __syncwarp();
        if (owner){
            dt = copysignf(fminf(fabsf(off), DT_MAXF), off);
            wx[0*PPW + lane] = fmaf(-0.5f*dt, vx, px);
            wx[1*PPW + lane] = fmaf(-0.5f*dt, vy, py);
            wx[2*PPW + lane] = fmaf(-0.5f*dt, vz, pz);
            wx[3*PPW + lane] = tt - 0.5f*dt;
        }
        __syncwarp();
        mlp_fwd8(sm, stg, wx, i4, w*PPW, lane, h1, h2, b3x, b3y, b3z, vx, vy, vz);

#pragma unroll
        for (int j = 0; j < 3; j++){
            float jx, jy, jz;
            mlp_tan8(sm, stg, i4, j, lane, h1, h2, jx, jy, jz);
            jac[j*3+0] = jx; jac[j*3+1] = jy; jac[j*3+2] = jz;
        }

        if (owner){
            float dr[9];
#pragma unroll
            for (int o = 0; o < 3; o++)
#pragma unroll
                for (int c = 0; c < 3; c++)
                    dr[o*3+c] = jac[0+o]*D[0*3+c] + jac[3+o]*D[1*3+c] + jac[6+o]*D[2*3+c];
#pragma unroll
            for (int q = 0; q < 9; q++) D[q] = fmaf(-dt, dr[q], D[q]);
            px = fmaf(-dt, vx, px);
            py = fmaf(-dt, vy, py);
            pz = fmaf(-dt, vz, pz);
            tt  -= dt;
            off -= dt;
        }
    }

    if (valid){
        out[(size_t)myp*3 + 0] = px;
        out[(size_t)myp*3 + 1] = py;
        out[(size_t)myp*3 + 2] = pz;
        float* od = out + (size_t)n*3 + (size_t)myp*9;
#pragma unroll
        for (int q = 0; q < 9; q++) od[q] = D[q];
    }
}

extern "C" void kernel_launch(void* const* d_in, const int* in_sizes, int n_in,
                              void* d_out, int out_size)
{
    const float* code = (const float*)d_in[0];
    const float* pos  = (const float*)d_in[1];
    const float* t1   = (const float*)d_in[2];
    const float* t2   = (const float*)d_in[3];
    const float* W1   = (const float*)d_in[4];
    const float* b1   = (const float*)d_in[5];
    const float* W2   = (const float*)d_in[6];
    const float* b2   = (const float*)d_in[7];
    const float* W3   = (const float*)d_in[8];
    const float* b3   = (const float*)d_in[9];

    const int n = in_sizes[2];                  // t1 has N elements
    const int blocks = (n + PPB - 1) / PPB;
    const size_t smem_bytes = (size_t)SM_TOTAL * sizeof(float);

    // bucket points by required step count (counting sort, 4 tiny kernels)
    k_zero<<<1, 32>>>();
    k_hist<<<(n + 255)/256, 256>>>(t1, t2, n);
    k_prefix<<<1, 32>>>();
    k_scatter<<<(n + 255)/256, 256>>>(t1, t2, n);

    cudaFuncSetAttribute(velwarp_kernel,
                         cudaFuncAttributeMaxDynamicSharedMemorySize,
                         (int)smem_bytes);

    velwarp_kernel<<<blocks, THREADS, smem_bytes>>>(
        code, pos, t1, t2, W1, b1, W2, b2, W3, b3, (float*)d_out, n);
}